// round 2
// baseline (speedup 1.0000x reference)
#include <cuda_runtime.h>
#include <cuda_bf16.h>
#include <cstdint>
#include <math.h>

#define Bsz  4
#define CIN  256
#define COUT 128
#define HW   4096   // 64*64

// ---------------- device scratch (no allocations allowed) ----------------
__device__ float g_xt[Bsz * HW * CIN];        // NHWC x  (16 MB)
__device__ float g_off[Bsz][27][HW];          // dy(0-8), dx(9-17), m(18-26)
__device__ float g_out1[Bsz][COUT][HW];       // deform conv output (pre-BN1)
__device__ float g_wT[2304 * COUT];           // dcn_w^T: [c*9+k][o]
__device__ float g_wT2[16 * COUT * COUT];     // [ky*4+kx][c][o] = up_w[c][o][3-ky][3-kx]
__device__ float g_bn1s[COUT], g_bn1b[COUT];
__device__ float g_bn2s[COUT], g_bn2b[COUT];

// ---------------- weight prep ----------------
__global__ void prep_kernel(const float* __restrict__ dcn_w,
                            const float* __restrict__ up_w) {
    int i = blockIdx.x * blockDim.x + threadIdx.x;
    if (i < 2304 * COUT) {
        int ck = i >> 7, o = i & 127;
        g_wT[i] = dcn_w[o * 2304 + ck];
    }
    if (i < 16 * COUT * COUT) {
        int o  = i & 127;
        int c  = (i >> 7) & 127;
        int kk = i >> 14;               // ky*4+kx
        int ky = kk >> 2, kx = kk & 3;
        g_wT2[i] = up_w[((c * COUT + o) * 4 + (3 - ky)) * 4 + (3 - kx)];
    }
}

// ---------------- NCHW -> NHWC transpose of x ----------------
__global__ void nhwc_kernel(const float* __restrict__ x) {
    __shared__ float t[32][33];
    int b  = blockIdx.z;
    int p0 = blockIdx.x * 32;
    int c0 = blockIdx.y * 32;
    int tx = threadIdx.x, ty = threadIdx.y;
#pragma unroll
    for (int i = 0; i < 4; i++)
        t[ty + i * 8][tx] = x[((size_t)(b * CIN + c0 + ty + i * 8)) * HW + p0 + tx];
    __syncthreads();
#pragma unroll
    for (int i = 0; i < 4; i++)
        g_xt[((size_t)(b * HW + p0 + ty + i * 8)) * CIN + c0 + tx] = t[tx][ty + i * 8];
}

// ---------------- offset conv: 3x3, 256 -> 27, pad 1 ----------------
// grid = B*64 (block per (b,row)), block = 512 = 8 channel-groups x 64 cols
#define OG 8
__global__ void offset_conv_kernel(const float* __restrict__ x,
                                   const float* __restrict__ off_w,
                                   const float* __restrict__ off_b) {
    int bh = blockIdx.x;
    int b = bh >> 6, h = bh & 63;
    int g = threadIdx.x >> 6;       // 0..7
    int w = threadIdx.x & 63;       // column
    __shared__ float srow[OG][3][64];
    __shared__ float sws[OG][324];  // 27 oc * 12 (pad from 9)
    __shared__ float red[OG][64];

    float acc[27];
#pragma unroll
    for (int i = 0; i < 27; i++) acc[i] = 0.f;

    const float* xb = x + (size_t)b * CIN * HW;
    for (int cc = 0; cc < CIN / OG; cc++) {     // 32 iters
        int c = g * (CIN / OG) + cc;
#pragma unroll
        for (int r = 0; r < 3; r++) {
            int hh = h + r - 1;
            srow[g][r][w] = (hh >= 0 && hh < 64) ? xb[(size_t)c * HW + hh * 64 + w] : 0.f;
        }
        const float* wc = off_w + c * 9;
        for (int j = w; j < 243; j += 64) {
            int oc = j / 9, tap = j - oc * 9;
            sws[g][oc * 12 + tap] = wc[(size_t)oc * (CIN * 9) + tap];
        }
        __syncthreads();
        float xv[9];
#pragma unroll
        for (int tap = 0; tap < 9; tap++) {
            int col = w + (tap % 3) - 1;
            xv[tap] = (col >= 0 && col < 64) ? srow[g][tap / 3][col] : 0.f;
        }
#pragma unroll
        for (int oc = 0; oc < 27; oc++) {
            const float4* wv = (const float4*)&sws[g][oc * 12];
            float4 w0 = wv[0], w1 = wv[1], w2 = wv[2];
            float a = acc[oc];
            a = fmaf(w0.x, xv[0], a); a = fmaf(w0.y, xv[1], a);
            a = fmaf(w0.z, xv[2], a); a = fmaf(w0.w, xv[3], a);
            a = fmaf(w1.x, xv[4], a); a = fmaf(w1.y, xv[5], a);
            a = fmaf(w1.z, xv[6], a); a = fmaf(w1.w, xv[7], a);
            a = fmaf(w2.x, xv[8], a);
            acc[oc] = a;
        }
        __syncthreads();
    }
    // reduce over the 8 channel groups
    for (int oc = 0; oc < 27; oc++) {
        red[g][w] = acc[oc];
        __syncthreads();
        if (g == 0) {
            float v = red[0][w] + red[1][w] + red[2][w] + red[3][w]
                    + red[4][w] + red[5][w] + red[6][w] + red[7][w] + off_b[oc];
            if (oc >= 18) v = 1.f / (1.f + __expf(-v));
            g_off[b][oc][h * 64 + w] = v;
        }
        __syncthreads();
    }
}

// ---------------- deformable conv implicit GEMM ----------------
// grid = B*64 (block per (b, row) = 64 pixels), block = 128 threads (thread = oc)
#define SSP 68   // padded ssam row stride (floats), 16B-aligned
__global__ void __launch_bounds__(128) deform_kernel(const float* __restrict__ dcn_b) {
    int blk = blockIdx.x;
    int b = blk >> 6;
    int h = blk & 63;
    int p0 = h << 6;                // 64 consecutive pixels (one row)
    int tid = threadIdx.x;

    __shared__ int4  sidx[576];                    // corner pixel indices per (p,k)
    __shared__ float4 swt[576];                    // corner weights * m
    __shared__ __align__(16) float ssam[72 * SSP]; // sampled chunk [ck][p]

    // Phase A: bilinear corner setup
    for (int e = tid; e < 576; e += 128) {
        int p = e / 9;
        int k = e - 9 * p;
        float dy = g_off[b][k][p0 + p];
        float dx = g_off[b][9 + k][p0 + p];
        float m  = g_off[b][18 + k][p0 + p];
        float py = dy + (float)(k / 3 - 1 + h);
        float px = dx + (float)(k % 3 - 1 + p);
        float y0f = floorf(py), x0f = floorf(px);
        int y0 = (int)y0f, x0i = (int)x0f;
        float wy = py - y0f, wx = px - x0f;
        float w00 = (1.f - wy) * (1.f - wx) * m;
        float w01 = (1.f - wy) * wx * m;
        float w10 = wy * (1.f - wx) * m;
        float w11 = wy * wx * m;
        int y1 = y0 + 1, x1i = x0i + 1;
        bool y0v = (unsigned)y0  < 64u, y1v = (unsigned)y1  < 64u;
        bool x0v = (unsigned)x0i < 64u, x1v = (unsigned)x1i < 64u;
        int y0c = min(max(y0, 0), 63),  y1c = min(max(y1, 0), 63);
        int x0c = min(max(x0i, 0), 63), x1c = min(max(x1i, 0), 63);
        sidx[e] = make_int4(y0c * 64 + x0c, y0c * 64 + x1c,
                            y1c * 64 + x0c, y1c * 64 + x1c);
        swt[e] = make_float4(y0v && x0v ? w00 : 0.f,
                             y0v && x1v ? w01 : 0.f,
                             y1v && x0v ? w10 : 0.f,
                             y1v && x1v ? w11 : 0.f);
    }
    __syncthreads();

    unsigned long long acc[32];
#pragma unroll
    for (int i = 0; i < 32; i++) acc[i] = 0ull;

    unsigned sbase = (unsigned)__cvta_generic_to_shared(ssam);
    const float* xtb = g_xt + (size_t)b * HW * CIN;

#pragma unroll 1
    for (int cb = 0; cb < 32; cb++) {           // 8 channels per chunk
        // gather into ssam[cc*9+k][p] for 8 channels
        for (int e = tid; e < 576; e += 128) {
            int p = e / 9;
            int k = e - 9 * p;
            int4 id = sidx[e];
            float4 wt = swt[e];
            const float* base = xtb + cb * 8;
            const float4* a = (const float4*)(base + (size_t)id.x * CIN);
            const float4* bq = (const float4*)(base + (size_t)id.y * CIN);
            const float4* cq = (const float4*)(base + (size_t)id.z * CIN);
            const float4* dq = (const float4*)(base + (size_t)id.w * CIN);
            float4 a0 = a[0], a1 = a[1];
            float4 b0 = bq[0], b1 = bq[1];
            float4 c0 = cq[0], c1 = cq[1];
            float4 d0 = dq[0], d1 = dq[1];
            float v0 = wt.x*a0.x + wt.y*b0.x + wt.z*c0.x + wt.w*d0.x;
            float v1 = wt.x*a0.y + wt.y*b0.y + wt.z*c0.y + wt.w*d0.y;
            float v2 = wt.x*a0.z + wt.y*b0.z + wt.z*c0.z + wt.w*d0.z;
            float v3 = wt.x*a0.w + wt.y*b0.w + wt.z*c0.w + wt.w*d0.w;
            float v4 = wt.x*a1.x + wt.y*b1.x + wt.z*c1.x + wt.w*d1.x;
            float v5 = wt.x*a1.y + wt.y*b1.y + wt.z*c1.y + wt.w*d1.y;
            float v6 = wt.x*a1.z + wt.y*b1.z + wt.z*c1.z + wt.w*d1.z;
            float v7 = wt.x*a1.w + wt.y*b1.w + wt.z*c1.w + wt.w*d1.w;
            ssam[(0*9 + k) * SSP + p] = v0;
            ssam[(1*9 + k) * SSP + p] = v1;
            ssam[(2*9 + k) * SSP + p] = v2;
            ssam[(3*9 + k) * SSP + p] = v3;
            ssam[(4*9 + k) * SSP + p] = v4;
            ssam[(5*9 + k) * SSP + p] = v5;
            ssam[(6*9 + k) * SSP + p] = v6;
            ssam[(7*9 + k) * SSP + p] = v7;
        }
        __syncthreads();
        // GEMM: acc[pixel-pairs] += w[ck][o] * ssam[ck][p]  (packed f32x2)
        const float* wp = g_wT + (size_t)cb * 72 * 128 + tid;
        for (int ckl = 0; ckl < 72; ckl++) {
            float wv = __ldg(wp + ckl * 128);
            unsigned long long wpk;
            asm("mov.b64 %0, {%1, %1};" : "=l"(wpk) : "f"(wv));
            unsigned a = sbase + ckl * (SSP * 4);
#pragma unroll
            for (int q = 0; q < 16; q++) {
                unsigned long long sa, sb;
                asm volatile("ld.shared.v2.b64 {%0, %1}, [%2];"
                             : "=l"(sa), "=l"(sb) : "r"(a + q * 16));
                asm("fma.rn.f32x2 %0, %1, %2, %0;" : "+l"(acc[2*q])   : "l"(wpk), "l"(sa));
                asm("fma.rn.f32x2 %0, %1, %2, %0;" : "+l"(acc[2*q+1]) : "l"(wpk), "l"(sb));
            }
        }
        __syncthreads();
    }

    float bias = dcn_b[tid];
    float* orow = &g_out1[b][tid][p0];
#pragma unroll
    for (int q = 0; q < 16; q++) {
        float e0, e1, e2, e3;
        asm("mov.b64 {%0, %1}, %2;" : "=f"(e0), "=f"(e1) : "l"(acc[2*q]));
        asm("mov.b64 {%0, %1}, %2;" : "=f"(e2), "=f"(e3) : "l"(acc[2*q+1]));
        ((float4*)orow)[q] = make_float4(e0 + bias, e1 + bias, e2 + bias, e3 + bias);
    }
}

// ---------------- BN stats (biased variance over B,H,W) ----------------
__global__ void bn_stats_kernel(const float* __restrict__ ext,
                                const float* __restrict__ gamma,
                                const float* __restrict__ beta,
                                int which) {
    int c = blockIdx.x;
    const float* data = (which == 0) ? &g_out1[0][0][0] : ext;
    int HWl = (which == 0) ? 4096 : 16384;
    float s = 0.f, s2 = 0.f;
    for (int b = 0; b < 4; b++) {
        const float4* p = (const float4*)(data + (size_t)(b * 128 + c) * HWl);
        for (int i = threadIdx.x; i < HWl / 4; i += 256) {
            float4 v = p[i];
            s  += v.x + v.y + v.z + v.w;
            s2 += v.x*v.x + v.y*v.y + v.z*v.z + v.w*v.w;
        }
    }
    __shared__ float rs[256], rq[256];
    rs[threadIdx.x] = s; rq[threadIdx.x] = s2;
    __syncthreads();
    for (int st = 128; st > 0; st >>= 1) {
        if (threadIdx.x < st) {
            rs[threadIdx.x] += rs[threadIdx.x + st];
            rq[threadIdx.x] += rq[threadIdx.x + st];
        }
        __syncthreads();
    }
    if (threadIdx.x == 0) {
        float n  = 4.0f * (float)HWl;
        float mu = rs[0] / n;
        float var = rq[0] / n - mu * mu;
        float sc = gamma[c] * rsqrtf(var + 1e-5f);
        float sh = beta[c] - mu * sc;
        if (which == 0) { g_bn1s[c] = sc; g_bn1b[c] = sh; }
        else            { g_bn2s[c] = sc; g_bn2b[c] = sh; }
    }
}

// ---------------- transposed conv (stride 2, 4x4, pad 2) as parity GEMMs ----
// grid = 1024: b(4) x parity(4) x u(64). block = 128 threads (thread = oc)
__global__ void __launch_bounds__(128) transp_kernel(float* __restrict__ out) {
    int blk = blockIdx.x;
    int u   = blk & 63;
    int par = (blk >> 6) & 3;
    int b   = blk >> 8;
    int py = par >> 1, px = par & 1;
    int tid = threadIdx.x;

    __shared__ float srow[16 * 2 * 64];              // [ci][t][col], BN1+ReLU applied
    __shared__ __align__(16) float ssam[64 * SSP];   // [ck=ci*4+t*2+s][p]

    unsigned long long acc[32];
#pragma unroll
    for (int i = 0; i < 32; i++) acc[i] = 0ull;

    unsigned sbase = (unsigned)__cvta_generic_to_shared(ssam);

#pragma unroll 1
    for (int cb = 0; cb < 8; cb++) {                 // 16 channels per chunk
        // stage raw rows with fused BN1 + ReLU (float4 granularity)
        for (int e = tid; e < 16 * 2 * 16; e += 128) {
            int ci = e >> 5;
            int t  = (e >> 4) & 1;
            int f4 = e & 15;
            int c  = cb * 16 + ci;
            int row = u + py - 1 + t;
            float4 v = make_float4(0.f, 0.f, 0.f, 0.f);
            if (row >= 0 && row < 64) {
                float4 r = *(const float4*)&g_out1[b][c][row * 64 + f4 * 4];
                float sc = g_bn1s[c], sh = g_bn1b[c];
                v.x = fmaxf(r.x * sc + sh, 0.f);
                v.y = fmaxf(r.y * sc + sh, 0.f);
                v.z = fmaxf(r.z * sc + sh, 0.f);
                v.w = fmaxf(r.w * sc + sh, 0.f);
            }
            *(float4*)&srow[(ci * 2 + t) * 64 + f4 * 4] = v;
        }
        __syncthreads();
        // expand to ssam[ck][p] with column shift px-1+s
        for (int e = tid; e < 64 * 64; e += 128) {
            int ck = e >> 6;
            int p  = e & 63;
            int ci = ck >> 2;
            int t  = (ck >> 1) & 1;
            int s  = ck & 1;
            int col = p + px - 1 + s;
            float v = (col >= 0 && col < 64) ? srow[(ci * 2 + t) * 64 + col] : 0.f;
            ssam[ck * SSP + p] = v;
        }
        __syncthreads();
        // GEMM over 64 ck
#pragma unroll 1
        for (int ts = 0; ts < 4; ts++) {
            int t = ts >> 1, s = ts & 1;
            int kk = (py + 2 * t) * 4 + (px + 2 * s);
            const float* wp = g_wT2 + (size_t)kk * 16384 + cb * 16 * 128 + tid;
            for (int ci = 0; ci < 16; ci++) {
                float wv = __ldg(wp + ci * 128);
                unsigned long long wpk;
                asm("mov.b64 %0, {%1, %1};" : "=l"(wpk) : "f"(wv));
                int ck = ci * 4 + ts;
                unsigned a = sbase + ck * (SSP * 4);
#pragma unroll
                for (int q = 0; q < 16; q++) {
                    unsigned long long sa, sb;
                    asm volatile("ld.shared.v2.b64 {%0, %1}, [%2];"
                                 : "=l"(sa), "=l"(sb) : "r"(a + q * 16));
                    asm("fma.rn.f32x2 %0, %1, %2, %0;" : "+l"(acc[2*q])   : "l"(wpk), "l"(sa));
                    asm("fma.rn.f32x2 %0, %1, %2, %0;" : "+l"(acc[2*q+1]) : "l"(wpk), "l"(sb));
                }
            }
        }
        __syncthreads();
    }

    int y = 2 * u + py;
    float* orow = out + (((size_t)(b * 128 + tid) * 128 + y) * 128) + px;
#pragma unroll
    for (int q = 0; q < 16; q++) {
        float e0, e1, e2, e3;
        asm("mov.b64 {%0, %1}, %2;" : "=f"(e0), "=f"(e1) : "l"(acc[2*q]));
        asm("mov.b64 {%0, %1}, %2;" : "=f"(e2), "=f"(e3) : "l"(acc[2*q+1]));
        orow[(4*q + 0) * 2] = e0;
        orow[(4*q + 1) * 2] = e1;
        orow[(4*q + 2) * 2] = e2;
        orow[(4*q + 3) * 2] = e3;
    }
}

// ---------------- BN2 apply + ReLU, in place on d_out ----------------
__global__ void bn_apply_kernel(float* __restrict__ out) {
    int i = blockIdx.x * 256 + threadIdx.x;          // float4 index
    int c = (i >> 12) & 127;                         // 16384/4 float4 per channel
    float sc = g_bn2s[c], sh = g_bn2b[c];
    float4 v = ((float4*)out)[i];
    v.x = fmaxf(v.x * sc + sh, 0.f);
    v.y = fmaxf(v.y * sc + sh, 0.f);
    v.z = fmaxf(v.z * sc + sh, 0.f);
    v.w = fmaxf(v.w * sc + sh, 0.f);
    ((float4*)out)[i] = v;
}

// ---------------- launch ----------------
extern "C" void kernel_launch(void* const* d_in, const int* in_sizes, int n_in,
                              void* d_out, int out_size) {
    const float* x     = (const float*)d_in[0];
    const float* off_w = (const float*)d_in[1];
    const float* off_b = (const float*)d_in[2];
    const float* dcn_w = (const float*)d_in[3];
    const float* dcn_b = (const float*)d_in[4];
    const float* bn1_g = (const float*)d_in[5];
    const float* bn1_b = (const float*)d_in[6];
    const float* up_w  = (const float*)d_in[7];
    const float* bn2_g = (const float*)d_in[8];
    const float* bn2_b = (const float*)d_in[9];
    float* out = (float*)d_out;

    prep_kernel<<<1152, 256>>>(dcn_w, up_w);
    nhwc_kernel<<<dim3(128, 8, 4), dim3(32, 8)>>>(x);
    offset_conv_kernel<<<256, 512>>>(x, off_w, off_b);
    deform_kernel<<<256, 128>>>(dcn_b);
    bn_stats_kernel<<<128, 256>>>(nullptr, bn1_g, bn1_b, 0);
    transp_kernel<<<1024, 128>>>(out);
    bn_stats_kernel<<<128, 256>>>(out, bn2_g, bn2_b, 1);
    bn_apply_kernel<<<8192, 256>>>(out);
}

// round 3
// speedup vs baseline: 1.2717x; 1.2717x over previous
#include <cuda_runtime.h>
#include <cuda_bf16.h>
#include <cstdint>
#include <math.h>

#define Bsz  4
#define CIN  256
#define COUT 128
#define HW   4096   // 64*64

// ---------------- device scratch ----------------
__device__ float g_xt[Bsz * HW * CIN];        // NHWC x (16 MB)
__device__ float g_off[Bsz][27][HW];          // dy(0-8), dx(9-17), m(18-26)
__device__ float g_out1[Bsz][COUT][HW];       // deform conv output (pre-BN1)
__device__ float g_wT[2304 * COUT];           // dcn_w reordered: [cb][k][c][o]
__device__ float g_wT2[16 * COUT * COUT];     // [ky*4+kx][c][o] = up_w[c][o][3-ky][3-kx]
__device__ float g_bn1s[COUT], g_bn1b[COUT];
__device__ float g_bn2s[COUT], g_bn2b[COUT];
__device__ float g_psum[2][512][2];           // partial BN sums [which][c*4+b][s,s2]

// ---------------- weight prep ----------------
__global__ void prep_kernel(const float* __restrict__ dcn_w,
                            const float* __restrict__ up_w) {
    int i = blockIdx.x * blockDim.x + threadIdx.x;
    if (i < 2304 * COUT) {
        int ck = i >> 7, o = i & 127;
        int cb = ck / 144;            // 16-channel chunk
        int r  = ck - cb * 144;       // 0..143
        int k  = r >> 4;              // tap 0..8
        int c  = r & 15;              // channel within chunk
        int cg = cb * 16 + c;
        g_wT[i] = dcn_w[o * 2304 + cg * 9 + k];
    }
    if (i < 16 * COUT * COUT) {
        int o  = i & 127;
        int c  = (i >> 7) & 127;
        int kk = i >> 14;             // ky*4+kx
        int ky = kk >> 2, kx = kk & 3;
        g_wT2[i] = up_w[((c * COUT + o) * 4 + (3 - ky)) * 4 + (3 - kx)];
    }
}

// ---------------- NCHW -> NHWC transpose of x ----------------
__global__ void nhwc_kernel(const float* __restrict__ x) {
    __shared__ float t[32][33];
    int b  = blockIdx.z;
    int p0 = blockIdx.x * 32;
    int c0 = blockIdx.y * 32;
    int tx = threadIdx.x, ty = threadIdx.y;
#pragma unroll
    for (int i = 0; i < 4; i++)
        t[ty + i * 8][tx] = x[((size_t)(b * CIN + c0 + ty + i * 8)) * HW + p0 + tx];
    __syncthreads();
#pragma unroll
    for (int i = 0; i < 4; i++)
        g_xt[((size_t)(b * HW + p0 + ty + i * 8)) * CIN + c0 + tx] = t[tx][ty + i * 8];
}

// ---------------- offset conv: 3x3, 256 -> 27, pad 1 ----------------
#define OG 8
__global__ void offset_conv_kernel(const float* __restrict__ x,
                                   const float* __restrict__ off_w,
                                   const float* __restrict__ off_b) {
    int bh = blockIdx.x;
    int b = bh >> 6, h = bh & 63;
    int g = threadIdx.x >> 6;
    int w = threadIdx.x & 63;
    __shared__ float srow[OG][3][64];
    __shared__ float sws[OG][324];
    __shared__ float red[OG][64];

    float acc[27];
#pragma unroll
    for (int i = 0; i < 27; i++) acc[i] = 0.f;

    const float* xb = x + (size_t)b * CIN * HW;
    for (int cc = 0; cc < CIN / OG; cc++) {
        int c = g * (CIN / OG) + cc;
#pragma unroll
        for (int r = 0; r < 3; r++) {
            int hh = h + r - 1;
            srow[g][r][w] = (hh >= 0 && hh < 64) ? xb[(size_t)c * HW + hh * 64 + w] : 0.f;
        }
        const float* wc = off_w + c * 9;
        for (int j = w; j < 243; j += 64) {
            int oc = j / 9, tap = j - oc * 9;
            sws[g][oc * 12 + tap] = wc[(size_t)oc * (CIN * 9) + tap];
        }
        __syncthreads();
        float xv[9];
#pragma unroll
        for (int tap = 0; tap < 9; tap++) {
            int col = w + (tap % 3) - 1;
            xv[tap] = (col >= 0 && col < 64) ? srow[g][tap / 3][col] : 0.f;
        }
#pragma unroll
        for (int oc = 0; oc < 27; oc++) {
            const float4* wv = (const float4*)&sws[g][oc * 12];
            float4 w0 = wv[0], w1 = wv[1], w2 = wv[2];
            float a = acc[oc];
            a = fmaf(w0.x, xv[0], a); a = fmaf(w0.y, xv[1], a);
            a = fmaf(w0.z, xv[2], a); a = fmaf(w0.w, xv[3], a);
            a = fmaf(w1.x, xv[4], a); a = fmaf(w1.y, xv[5], a);
            a = fmaf(w1.z, xv[6], a); a = fmaf(w1.w, xv[7], a);
            a = fmaf(w2.x, xv[8], a);
            acc[oc] = a;
        }
        __syncthreads();
    }
    for (int oc = 0; oc < 27; oc++) {
        red[g][w] = acc[oc];
        __syncthreads();
        if (g == 0) {
            float v = red[0][w] + red[1][w] + red[2][w] + red[3][w]
                    + red[4][w] + red[5][w] + red[6][w] + red[7][w] + off_b[oc];
            if (oc >= 18) v = 1.f / (1.f + __expf(-v));
            g_off[b][oc][h * 64 + w] = v;
        }
        __syncthreads();
    }
}

// ---------------- deformable conv implicit GEMM (v2) ----------------
// grid = B*128 (block = 32 pixels = half row), block = 128 threads.
// thread = (oc0 = tid&63 handling oc0 and oc0+64) x (16-pixel half = tid>>6).
#define SSP2 36   // ssam row stride for 32 px (16B-aligned)
__global__ void __launch_bounds__(128) deform_kernel(const float* __restrict__ dcn_b) {
    int blk = blockIdx.x;
    int b = blk >> 7;
    int t = blk & 127;
    int h = t >> 1;
    int w0 = (t & 1) << 5;
    int p0 = h * 64 + w0;
    int tid = threadIdx.x;

    __shared__ int4  sidx[288];                       // e = k*32 + p
    __shared__ float4 swt[288];
    __shared__ __align__(16) float ssam[144 * SSP2];  // [k*16+c][p]

    // Phase A: bilinear corner setup
    for (int e = tid; e < 288; e += 128) {
        int k = e >> 5, p = e & 31;
        float dy = g_off[b][k][p0 + p];
        float dx = g_off[b][9 + k][p0 + p];
        float m  = g_off[b][18 + k][p0 + p];
        float py = dy + (float)(k / 3 - 1 + h);
        float px = dx + (float)(k % 3 - 1 + w0 + p);
        float y0f = floorf(py), x0f = floorf(px);
        int y0 = (int)y0f, x0i = (int)x0f;
        float wy = py - y0f, wx = px - x0f;
        float w00 = (1.f - wy) * (1.f - wx) * m;
        float w01 = (1.f - wy) * wx * m;
        float w10 = wy * (1.f - wx) * m;
        float w11 = wy * wx * m;
        int y1 = y0 + 1, x1i = x0i + 1;
        bool y0v = (unsigned)y0  < 64u, y1v = (unsigned)y1  < 64u;
        bool x0v = (unsigned)x0i < 64u, x1v = (unsigned)x1i < 64u;
        int y0c = min(max(y0, 0), 63),  y1c = min(max(y1, 0), 63);
        int x0c = min(max(x0i, 0), 63), x1c = min(max(x1i, 0), 63);
        sidx[e] = make_int4(y0c * 64 + x0c, y0c * 64 + x1c,
                            y1c * 64 + x0c, y1c * 64 + x1c);
        swt[e] = make_float4(y0v && x0v ? w00 : 0.f,
                             y0v && x1v ? w01 : 0.f,
                             y1v && x0v ? w10 : 0.f,
                             y1v && x1v ? w11 : 0.f);
    }
    __syncthreads();

    int oc0 = tid & 63;
    int pbase = (tid >> 6) << 4;      // 0 or 16

    unsigned long long acc[16];       // [0..7]=oc0, [8..15]=oc0+64 (8 px-pairs each)
#pragma unroll
    for (int i = 0; i < 16; i++) acc[i] = 0ull;

    unsigned sbase = (unsigned)__cvta_generic_to_shared(ssam);
    const float* xtb = g_xt + (size_t)b * HW * CIN;

#pragma unroll 1
    for (int cb = 0; cb < 16; cb++) {           // 16 channels per chunk
        // gather: item = (k, p4, c); lanes cover 16 channels x 2 p-groups
        for (int it = tid; it < 1152; it += 128) {
            int c  = it & 15;
            int kp = it >> 4;          // 0..71
            int k  = kp >> 3;
            int p4 = kp & 7;
            const float* xc = xtb + cb * 16 + c;
            float4 v;
            float* vp = &v.x;
#pragma unroll
            for (int j = 0; j < 4; j++) {
                int e = k * 32 + p4 * 4 + j;
                int4 id = sidx[e];
                float4 wt = swt[e];
                float r =      wt.x * __ldg(xc + id.x * CIN);
                r = fmaf(wt.y, __ldg(xc + id.y * CIN), r);
                r = fmaf(wt.z, __ldg(xc + id.z * CIN), r);
                r = fmaf(wt.w, __ldg(xc + id.w * CIN), r);
                vp[j] = r;
            }
            *(float4*)&ssam[(k * 16 + c) * SSP2 + p4 * 4] = v;
        }
        __syncthreads();
        // GEMM over 144 K-rows
        const float* wp = g_wT + (size_t)cb * 144 * 128 + oc0;
        for (int ckl = 0; ckl < 144; ckl++) {
            float wv0 = __ldg(wp + ckl * 128);
            float wv1 = __ldg(wp + ckl * 128 + 64);
            unsigned long long w0pk, w1pk;
            asm("mov.b64 %0, {%1, %1};" : "=l"(w0pk) : "f"(wv0));
            asm("mov.b64 %0, {%1, %1};" : "=l"(w1pk) : "f"(wv1));
            unsigned a = sbase + (ckl * SSP2 + pbase) * 4;
#pragma unroll
            for (int q = 0; q < 4; q++) {
                unsigned long long sa, sb;
                asm volatile("ld.shared.v2.b64 {%0, %1}, [%2];"
                             : "=l"(sa), "=l"(sb) : "r"(a + q * 16));
                asm("fma.rn.f32x2 %0, %1, %2, %0;" : "+l"(acc[2*q])     : "l"(w0pk), "l"(sa));
                asm("fma.rn.f32x2 %0, %1, %2, %0;" : "+l"(acc[2*q+1])   : "l"(w0pk), "l"(sb));
                asm("fma.rn.f32x2 %0, %1, %2, %0;" : "+l"(acc[8+2*q])   : "l"(w1pk), "l"(sa));
                asm("fma.rn.f32x2 %0, %1, %2, %0;" : "+l"(acc[8+2*q+1]) : "l"(w1pk), "l"(sb));
            }
        }
        __syncthreads();
    }

    float bias0 = dcn_b[oc0], bias1 = dcn_b[oc0 + 64];
    float* o0 = &g_out1[b][oc0][p0 + pbase];
    float* o1 = &g_out1[b][oc0 + 64][p0 + pbase];
#pragma unroll
    for (int q = 0; q < 4; q++) {
        float e0, e1, e2, e3;
        asm("mov.b64 {%0, %1}, %2;" : "=f"(e0), "=f"(e1) : "l"(acc[2*q]));
        asm("mov.b64 {%0, %1}, %2;" : "=f"(e2), "=f"(e3) : "l"(acc[2*q+1]));
        ((float4*)o0)[q] = make_float4(e0 + bias0, e1 + bias0, e2 + bias0, e3 + bias0);
        asm("mov.b64 {%0, %1}, %2;" : "=f"(e0), "=f"(e1) : "l"(acc[8+2*q]));
        asm("mov.b64 {%0, %1}, %2;" : "=f"(e2), "=f"(e3) : "l"(acc[8+2*q+1]));
        ((float4*)o1)[q] = make_float4(e0 + bias1, e1 + bias1, e2 + bias1, e3 + bias1);
    }
}

// ---------------- BN stats: 2-stage deterministic reduction ----------------
__global__ void bn_partial_kernel(const float* __restrict__ ext, int which) {
    int bx = blockIdx.x;             // 512 = 128 c * 4 b
    int c = bx >> 2, b = bx & 3;
    const float* plane = which ? ext + (size_t)(b * 128 + c) * 16384
                               : &g_out1[b][c][0];
    int n4 = which ? 4096 : 1024;
    float s = 0.f, s2 = 0.f;
    const float4* p4 = (const float4*)plane;
    for (int i = threadIdx.x; i < n4; i += 128) {
        float4 v = p4[i];
        s  += v.x + v.y + v.z + v.w;
        s2 += v.x*v.x + v.y*v.y + v.z*v.z + v.w*v.w;
    }
    __shared__ float rs[128], rq[128];
    rs[threadIdx.x] = s; rq[threadIdx.x] = s2;
    __syncthreads();
    for (int st = 64; st > 0; st >>= 1) {
        if (threadIdx.x < st) {
            rs[threadIdx.x] += rs[threadIdx.x + st];
            rq[threadIdx.x] += rq[threadIdx.x + st];
        }
        __syncthreads();
    }
    if (threadIdx.x == 0) {
        g_psum[which][bx][0] = rs[0];
        g_psum[which][bx][1] = rq[0];
    }
}

__global__ void bn_final_kernel(const float* __restrict__ gamma,
                                const float* __restrict__ beta, int which) {
    int c = threadIdx.x;
    float s = 0.f, s2 = 0.f;
#pragma unroll
    for (int b = 0; b < 4; b++) {
        s  += g_psum[which][c * 4 + b][0];
        s2 += g_psum[which][c * 4 + b][1];
    }
    float n  = which ? 65536.f : 16384.f;
    float mu = s / n;
    float var = s2 / n - mu * mu;
    float sc = gamma[c] * rsqrtf(var + 1e-5f);
    float sh = beta[c] - mu * sc;
    if (which == 0) { g_bn1s[c] = sc; g_bn1b[c] = sh; }
    else            { g_bn2s[c] = sc; g_bn2b[c] = sh; }
}

// ---------------- transposed conv as parity GEMMs (v2: 2 oc/thread) ----------
#define SSP 68
__global__ void __launch_bounds__(128) transp_kernel(float* __restrict__ out) {
    int blk = blockIdx.x;
    int u   = blk & 63;
    int par = (blk >> 6) & 3;
    int b   = blk >> 8;
    int py = par >> 1, px = par & 1;
    int tid = threadIdx.x;

    __shared__ float srow[16 * 2 * 64];              // [ci][t][col], BN1+ReLU applied
    __shared__ __align__(16) float ssam[64 * SSP];   // [ck=ci*4+t*2+s][p]

    int oc0 = tid & 63;
    int pbase = (tid >> 6) << 5;      // 0 or 32

    unsigned long long acc[32];       // [0..15]=oc0, [16..31]=oc0+64
#pragma unroll
    for (int i = 0; i < 32; i++) acc[i] = 0ull;

    unsigned sbase = (unsigned)__cvta_generic_to_shared(ssam);

#pragma unroll 1
    for (int cb = 0; cb < 8; cb++) {                 // 16 channels per chunk
        // stage rows with fused BN1 + ReLU
        for (int e = tid; e < 16 * 2 * 16; e += 128) {
            int ci = e >> 5;
            int tt = (e >> 4) & 1;
            int f4 = e & 15;
            int c  = cb * 16 + ci;
            int row = u + py - 1 + tt;
            float4 v = make_float4(0.f, 0.f, 0.f, 0.f);
            if (row >= 0 && row < 64) {
                float4 r = *(const float4*)&g_out1[b][c][row * 64 + f4 * 4];
                float sc = g_bn1s[c], sh = g_bn1b[c];
                v.x = fmaxf(r.x * sc + sh, 0.f);
                v.y = fmaxf(r.y * sc + sh, 0.f);
                v.z = fmaxf(r.z * sc + sh, 0.f);
                v.w = fmaxf(r.w * sc + sh, 0.f);
            }
            *(float4*)&srow[(ci * 2 + tt) * 64 + f4 * 4] = v;
        }
        __syncthreads();
        // expand to ssam[ck][p] with column shift px-1+s
        for (int e = tid; e < 64 * 64; e += 128) {
            int ck = e >> 6;
            int p  = e & 63;
            int ci = ck >> 2;
            int tt = (ck >> 1) & 1;
            int s  = ck & 1;
            int col = p + px - 1 + s;
            float v = (col >= 0 && col < 64) ? srow[(ci * 2 + tt) * 64 + col] : 0.f;
            ssam[ck * SSP + p] = v;
        }
        __syncthreads();
        // GEMM over 64 ck
#pragma unroll 1
        for (int ts = 0; ts < 4; ts++) {
            int tt = ts >> 1, s = ts & 1;
            int kk = (py + 2 * tt) * 4 + (px + 2 * s);
            const float* wp = g_wT2 + (size_t)kk * 16384 + cb * 16 * 128 + oc0;
            for (int ci = 0; ci < 16; ci++) {
                float wv0 = __ldg(wp + ci * 128);
                float wv1 = __ldg(wp + ci * 128 + 64);
                unsigned long long w0pk, w1pk;
                asm("mov.b64 %0, {%1, %1};" : "=l"(w0pk) : "f"(wv0));
                asm("mov.b64 %0, {%1, %1};" : "=l"(w1pk) : "f"(wv1));
                int ck = ci * 4 + ts;
                unsigned a = sbase + (ck * SSP + pbase) * 4;
#pragma unroll
                for (int q = 0; q < 8; q++) {
                    unsigned long long sa, sb;
                    asm volatile("ld.shared.v2.b64 {%0, %1}, [%2];"
                                 : "=l"(sa), "=l"(sb) : "r"(a + q * 16));
                    asm("fma.rn.f32x2 %0, %1, %2, %0;" : "+l"(acc[2*q])      : "l"(w0pk), "l"(sa));
                    asm("fma.rn.f32x2 %0, %1, %2, %0;" : "+l"(acc[2*q+1])    : "l"(w0pk), "l"(sb));
                    asm("fma.rn.f32x2 %0, %1, %2, %0;" : "+l"(acc[16+2*q])   : "l"(w1pk), "l"(sa));
                    asm("fma.rn.f32x2 %0, %1, %2, %0;" : "+l"(acc[16+2*q+1]) : "l"(w1pk), "l"(sb));
                }
            }
        }
        __syncthreads();
    }

    int y = 2 * u + py;
    float* o0 = out + (((size_t)(b * 128 + oc0)      * 128 + y) * 128) + px + 2 * pbase;
    float* o1 = out + (((size_t)(b * 128 + oc0 + 64) * 128 + y) * 128) + px + 2 * pbase;
#pragma unroll
    for (int q = 0; q < 8; q++) {
        float e0, e1, e2, e3;
        asm("mov.b64 {%0, %1}, %2;" : "=f"(e0), "=f"(e1) : "l"(acc[2*q]));
        asm("mov.b64 {%0, %1}, %2;" : "=f"(e2), "=f"(e3) : "l"(acc[2*q+1]));
        o0[(4*q + 0) * 2] = e0; o0[(4*q + 1) * 2] = e1;
        o0[(4*q + 2) * 2] = e2; o0[(4*q + 3) * 2] = e3;
        asm("mov.b64 {%0, %1}, %2;" : "=f"(e0), "=f"(e1) : "l"(acc[16+2*q]));
        asm("mov.b64 {%0, %1}, %2;" : "=f"(e2), "=f"(e3) : "l"(acc[16+2*q+1]));
        o1[(4*q + 0) * 2] = e0; o1[(4*q + 1) * 2] = e1;
        o1[(4*q + 2) * 2] = e2; o1[(4*q + 3) * 2] = e3;
    }
}

// ---------------- BN2 apply + ReLU, in place on d_out ----------------
__global__ void bn_apply_kernel(float* __restrict__ out) {
    int i = blockIdx.x * 256 + threadIdx.x;
    int c = (i >> 12) & 127;
    float sc = g_bn2s[c], sh = g_bn2b[c];
    float4 v = ((float4*)out)[i];
    v.x = fmaxf(v.x * sc + sh, 0.f);
    v.y = fmaxf(v.y * sc + sh, 0.f);
    v.z = fmaxf(v.z * sc + sh, 0.f);
    v.w = fmaxf(v.w * sc + sh, 0.f);
    ((float4*)out)[i] = v;
}

// ---------------- launch ----------------
extern "C" void kernel_launch(void* const* d_in, const int* in_sizes, int n_in,
                              void* d_out, int out_size) {
    const float* x     = (const float*)d_in[0];
    const float* off_w = (const float*)d_in[1];
    const float* off_b = (const float*)d_in[2];
    const float* dcn_w = (const float*)d_in[3];
    const float* dcn_b = (const float*)d_in[4];
    const float* bn1_g = (const float*)d_in[5];
    const float* bn1_b = (const float*)d_in[6];
    const float* up_w  = (const float*)d_in[7];
    const float* bn2_g = (const float*)d_in[8];
    const float* bn2_b = (const float*)d_in[9];
    float* out = (float*)d_out;

    prep_kernel<<<1152, 256>>>(dcn_w, up_w);
    nhwc_kernel<<<dim3(128, 8, 4), dim3(32, 8)>>>(x);
    offset_conv_kernel<<<256, 512>>>(x, off_w, off_b);
    deform_kernel<<<512, 128>>>(dcn_b);
    bn_partial_kernel<<<512, 128>>>(nullptr, 0);
    bn_final_kernel<<<1, 128>>>(bn1_g, bn1_b, 0);
    transp_kernel<<<1024, 128>>>(out);
    bn_partial_kernel<<<512, 128>>>(out, 1);
    bn_final_kernel<<<1, 128>>>(bn2_g, bn2_b, 1);
    bn_apply_kernel<<<8192, 256>>>(out);
}